// round 16
// baseline (speedup 1.0000x reference)
#include <cuda_runtime.h>
#include <cuda_bf16.h>
#include <cstdint>

#define NROWS 4096
#define DIM 256
#define DFF 512
#define NHEAD 8
#define DHEAD 64
#define NCHAIN 64
#define NBATCH 8
#define YW 1024
#define CH_STRIDE 256
#define BA_STRIDE 1024
#define KZ 12

// ================= mma.sync / cp.async helpers =================
__device__ __forceinline__ uint32_t smem_u32(const void* p) {
    uint32_t a;
    asm("{ .reg .u64 t; cvta.to.shared.u64 t, %1; cvt.u32.u64 %0, t; }" : "=r"(a) : "l"(p));
    return a;
}
__device__ __forceinline__ void mma_bf16(float* c, const uint32_t* a, const uint32_t* b) {
    asm volatile(
        "mma.sync.aligned.m16n8k16.row.col.f32.bf16.bf16.f32 "
        "{%0,%1,%2,%3}, {%4,%5,%6,%7}, {%8,%9}, {%0,%1,%2,%3};"
        : "+f"(c[0]), "+f"(c[1]), "+f"(c[2]), "+f"(c[3])
        : "r"(a[0]), "r"(a[1]), "r"(a[2]), "r"(a[3]), "r"(b[0]), "r"(b[1]));
}
__device__ __forceinline__ void ldsm_x4(uint32_t* r, uint32_t addr) {
    asm volatile("ldmatrix.sync.aligned.m8n8.x4.shared.b16 {%0,%1,%2,%3}, [%4];"
                 : "=r"(r[0]), "=r"(r[1]), "=r"(r[2]), "=r"(r[3]) : "r"(addr));
}
__device__ __forceinline__ void ldsm_x2(uint32_t* r, uint32_t addr) {
    asm volatile("ldmatrix.sync.aligned.m8n8.x2.shared.b16 {%0,%1}, [%2];"
                 : "=r"(r[0]), "=r"(r[1]) : "r"(addr));
}
__device__ __forceinline__ void ldsm_x4_t(uint32_t* r, uint32_t addr) {
    asm volatile("ldmatrix.sync.aligned.m8n8.x4.trans.shared.b16 {%0,%1,%2,%3}, [%4];"
                 : "=r"(r[0]), "=r"(r[1]), "=r"(r[2]), "=r"(r[3]) : "r"(addr));
}
__device__ __forceinline__ void ldsm_x2_t(uint32_t* r, uint32_t addr) {
    asm volatile("ldmatrix.sync.aligned.m8n8.x2.trans.shared.b16 {%0,%1}, [%2];"
                 : "=r"(r[0]), "=r"(r[1]) : "r"(addr));
}
__device__ __forceinline__ void cp_async16(uint32_t saddr, const void* g) {
    asm volatile("cp.async.cg.shared.global [%0], [%1], 16;" :: "r"(saddr), "l"(g));
}
#define CP_COMMIT() asm volatile("cp.async.commit_group;" ::: "memory")
#define CP_WAIT1()  asm volatile("cp.async.wait_group 1;" ::: "memory")
#define CP_WAIT0()  asm volatile("cp.async.wait_group 0;" ::: "memory")

#define SMS 40
#define KVS 72

// ================= scratch =================
__device__ float g_bmean[NBATCH * YW];
__device__ float g_Apart[KZ * NBATCH * NHEAD * 4096];
__device__ __nv_bfloat16 g_Ahi[NBATCH * NHEAD * 4096];
__device__ __nv_bfloat16 g_Alo[NBATCH * NHEAD * 4096];

__device__ __nv_bfloat16 g_khi[NROWS * DFF];
__device__ __nv_bfloat16 g_klo[NROWS * DFF];
__device__ __nv_bfloat16 g_vhi[NROWS * DFF];
__device__ __nv_bfloat16 g_vlo[NROWS * DFF];
__device__ __nv_bfloat16 g_qhi[NROWS * DFF];
__device__ __nv_bfloat16 g_qlo[NROWS * DFF];

__device__ __nv_bfloat16 g_lhi[NROWS * DIM];
__device__ __nv_bfloat16 g_llo[NROWS * DIM];
__device__ __nv_bfloat16 g_wthi[3 * DFF * DIM];
__device__ __nv_bfloat16 g_wtlo[3 * DFF * DIM];
__device__ __nv_bfloat16 g_yhi[NROWS * YW];
__device__ __nv_bfloat16 g_ylo[NROWS * YW];
__device__ __nv_bfloat16 g_wohi[DIM * YW];
__device__ __nv_bfloat16 g_wolo[DIM * YW];

__device__ int   g_list_chain[NCHAIN * CH_STRIDE];
__device__ int   g_list_batch[NBATCH * BA_STRIDE];
__device__ int   g_cnt_chain[NCHAIN];
__device__ int   g_cnt_batch[NBATCH];
__device__ float g_minv_chain[NCHAIN];
__device__ float g_minv_batch[NBATCH];

// ================= fused: mask-mode detect + list build + batch xsum + bmean =================
__global__ void __launch_bounds__(1024) build_all_kernel(
    const int* __restrict__ chain, const int* __restrict__ batch,
    const void* __restrict__ maskp,
    const float* __restrict__ local,
    const float* __restrict__ W_bias, const float* __restrict__ b_bias)
{
    int blk = blockIdx.x;
    bool isb = (blk < NBATCH);
    int s = isb ? blk : blk - NBATCH;
    const int* seg = isb ? batch : chain;
    int stride = isb ? BA_STRIDE : CH_STRIDE;
    int* list = isb ? g_list_batch : g_list_chain;
    int* cnts = isb ? g_cnt_batch : g_cnt_chain;
    float* minv = isb ? g_minv_batch : g_minv_chain;
    const unsigned char* mb = (const unsigned char*)maskp;
    const unsigned int*  mw = (const unsigned int*)maskp;

    int t = threadIdx.x;
    int w = t >> 5, lane = t & 31;
    __shared__ int woff[32];
    __shared__ int wred[32];
    __shared__ int sbase, snext;
    __shared__ int smode;
    __shared__ float sinv;
    __shared__ float xs4[4][DIM];
    __shared__ float xs[DIM];

    {
        int c = 0;
#pragma unroll
        for (int r = 0; r < NROWS / 1024; r++) c += (mb[r * 1024 + t] != 0);
        for (int o = 16; o > 0; o >>= 1) c += __shfl_down_sync(0xffffffffu, c, o);
        if (lane == 0) wred[w] = c;
        __syncthreads();
        if (w == 0) {
            int v = wred[lane];
            for (int o = 16; o > 0; o >>= 1) v += __shfl_down_sync(0xffffffffu, v, o);
            if (lane == 0) smode = (2 * v > NROWS) ? 1 : 0;
        }
    }
    if (t == 0) sbase = 0;
    int mcount = 0;
    __syncthreads();
    int mode = smode;

    for (int c = 0; c < NROWS / 1024; c++) {
        int i = c * 1024 + t;
        bool pred = (seg[i] == s);
        bool on = mode ? (mb[i] != 0) : (mw[i] != 0u);
        bool mk = pred && on;
        unsigned ball = __ballot_sync(0xffffffffu, pred);
        int wpre = __popc(ball & ((1u << lane) - 1u));
        if (lane == 0) woff[w] = __popc(ball);
        __syncthreads();
        if (w == 0) {
            int v = woff[lane];
            int sc = v;
            for (int o = 1; o < 32; o <<= 1) {
                int nb = __shfl_up_sync(0xffffffffu, sc, o);
                if (lane >= o) sc += nb;
            }
            woff[lane] = sbase + sc - v;
            if (lane == 31) snext = sbase + sc;
        }
        __syncthreads();
        if (pred) list[s * stride + woff[w] + wpre] = i | (mk ? 0x80000000 : 0);
        mcount += mk ? 1 : 0;
        if (t == 0) sbase = snext;
        __syncthreads();
    }

    for (int o = 16; o > 0; o >>= 1) mcount += __shfl_down_sync(0xffffffffu, mcount, o);
    if (lane == 0) wred[w] = mcount;
    __syncthreads();
    if (w == 0) {
        int v = wred[lane];
        for (int o = 16; o > 0; o >>= 1) v += __shfl_down_sync(0xffffffffu, v, o);
        if (lane == 0) {
            cnts[s] = sbase;
            float iv = 1.0f / fmaxf((float)v, 1e-6f);
            minv[s] = iv;
            sinv = iv;
        }
    }
    __syncthreads();

    if (!isb) return;

    int n = sbase;
    int quarter = t >> 8, col = t & 255;
    float a = 0.f;
    const int* L = list + s * stride;
    for (int m = quarter; m < n; m += 4) {
        int e = L[m];
        if (e < 0) a += local[(size_t)(e & 0x7fffffff) * DIM + col];
    }
    xs4[quarter][col] = a;
    __syncthreads();
    if (t < DIM) xs[t] = (xs4[0][t] + xs4[1][t]) + (xs4[2][t] + xs4[3][t]);
    __syncthreads();

    float inv = sinv;
    float acc = 0.f;
#pragma unroll 8
    for (int k = 0; k < DIM; k++) acc += xs[k] * W_bias[(size_t)k * YW + t];
    g_bmean[s * YW + t] = acc * inv + b_bias[t];
}

__device__ __forceinline__ float gelu_tanh(float x) {
    float x3 = x * x * x;
    float inner = 0.7978845608028654f * (x + 0.044715f * x3);
    return 0.5f * x * (1.0f + tanhf(inner));
}

__device__ __forceinline__ void split2(float x, __nv_bfloat16& h, __nv_bfloat16& l) {
    h = __float2bfloat16(x);
    l = __float2bfloat16(x - __bfloat162float(h));
}

// ================= fused prep =================
__global__ void prep_kernel(const float* __restrict__ X,
                            const float* __restrict__ Wk, const float* __restrict__ Wv,
                            const float* __restrict__ Wq, const float* __restrict__ Wo)
{
    int bid = blockIdx.x;
    int t = threadIdx.x;
    if (bid < 1024) {
        int i4 = (bid * 256 + t) * 4;
        float4 x = *(const float4*)(X + i4);
        __nv_bfloat16 h, l;
        split2(x.x, h, l); g_lhi[i4 + 0] = h; g_llo[i4 + 0] = l;
        split2(x.y, h, l); g_lhi[i4 + 1] = h; g_llo[i4 + 1] = l;
        split2(x.z, h, l); g_lhi[i4 + 2] = h; g_llo[i4 + 2] = l;
        split2(x.w, h, l); g_lhi[i4 + 3] = h; g_llo[i4 + 3] = l;
        return;
    }
    __shared__ float tile[32][33];
    int b = bid - 1024;
    int z = b / 512;
    int rem = b - z * 512;
    int nx0 = (rem & 15) * 32, ky0 = (rem >> 4) * 32;
    const float* W;
    int K, N, roff;
    __nv_bfloat16 *hi, *lo;
    if (z == 0)      { W = Wk; K = DIM; N = DFF; hi = g_wthi; lo = g_wtlo; roff = 0; }
    else if (z == 1) { W = Wv; K = DIM; N = DFF; hi = g_wthi; lo = g_wtlo; roff = DFF; }
    else if (z == 2) { W = Wq; K = DIM; N = DFF; hi = g_wthi; lo = g_wtlo; roff = 2 * DFF; }
    else             { W = Wo; K = YW;  N = DIM; hi = g_wohi; lo = g_wolo; roff = 0; }
    if (nx0 >= N || ky0 >= K) return;
    int tx = t & 31, ty = t >> 5;

#pragma unroll
    for (int r = 0; r < 4; r++) {
        int k = ky0 + ty + r * 8;
        tile[ty + r * 8][tx] = W[(size_t)k * N + nx0 + tx];
    }
    __syncthreads();
#pragma unroll
    for (int r = 0; r < 4; r++) {
        int n = nx0 + ty + r * 8;
        float x = tile[tx][ty + r * 8];
        __nv_bfloat16 h, l;
        split2(x, h, l);
        hi[(size_t)(roff + n) * K + ky0 + tx] = h;
        lo[(size_t)(roff + n) * K + ky0 + tx] = l;
    }
}

// ================= proj GEMM =================
#define PROJ_AS (128 * SMS)
#define PROJ_STB (PROJ_AS * 2)
#define PROJ_SMEM (8 * PROJ_AS * 2)
__global__ void __launch_bounds__(256) proj_mma_kernel(
    const float* __restrict__ bk, const float* __restrict__ bv, const float* __restrict__ bq)
{
    extern __shared__ __nv_bfloat16 smp[];
    __nv_bfloat16* sAh = smp;
    __nv_bfloat16* sAl = smp + 2 * PROJ_AS;
    __nv_bfloat16* sBh = smp + 4 * PROJ_AS;
    __nv_bfloat16* sBl = smp + 6 * PROJ_AS;

    int t = threadIdx.x, wid = t >> 5, lane = t & 31;
    int warp_m = wid & 1, warp_n = wid >> 1;
    int m0 = blockIdx.y * 128;
    int gn0 = blockIdx.x * 128;
    int sec = gn0 >> 9, wc = gn0 & 511;

    float acc[4][4][4];
#pragma unroll
    for (int i = 0; i < 4; i++)
#pragma unroll
        for (int j = 0; j < 4; j++)
#pragma unroll
            for (int e = 0; e < 4; e++) acc[i][j][e] = 0.f;

    uint32_t uAh = smem_u32(sAh), uAl = smem_u32(sAl);
    uint32_t uBh = smem_u32(sBh), uBl = smem_u32(sBl);

    int ldrow = t >> 2, ldq = t & 3;
    uint32_t so0 = (uint32_t)((ldrow * SMS + ldq * 8) * 2);
    uint32_t so1 = (uint32_t)(((ldrow + 64) * SMS + ldq * 8) * 2);
    const __nv_bfloat16* pA0h = g_lhi  + (size_t)(m0 + ldrow) * DIM + ldq * 8;
    const __nv_bfloat16* pA1h = g_lhi  + (size_t)(m0 + ldrow + 64) * DIM + ldq * 8;
    const __nv_bfloat16* pA0l = g_llo  + (size_t)(m0 + ldrow) * DIM + ldq * 8;
    const __nv_bfloat16* pA1l = g_llo  + (size_t)(m0 + ldrow + 64) * DIM + ldq * 8;
    const __nv_bfloat16* pB0h = g_wthi + (size_t)(gn0 + ldrow) * DIM + ldq * 8;
    const __nv_bfloat16* pB1h = g_wthi + (size_t)(gn0 + ldrow + 64) * DIM + ldq * 8;
    const __nv_bfloat16* pB0l = g_wtlo + (size_t)(gn0 + ldrow) * DIM + ldq * 8;
    const __nv_bfloat16* pB1l = g_wtlo + (size_t)(gn0 + ldrow + 64) * DIM + ldq * 8;

    int arow_a = warp_m * 64 + (lane & 15);
    int aksel  = (lane >> 4) * 8;
    int brow_b = warp_n * 32 + (lane & 7);
    int bksel  = ((lane >> 3) & 1) * 8;

#define PROJ_CP(st_, k0_) do { \
    uint32_t sb_ = (uint32_t)(st_) * PROJ_STB; \
    cp_async16(uAh + sb_ + so0, pA0h + (k0_)); \
    cp_async16(uAh + sb_ + so1, pA1h + (k0_)); \
    cp_async16(uAl + sb_ + so0, pA0l + (k0_)); \
    cp_async16(uAl + sb_ + so1, pA1l + (k0_)); \
    cp_async16(uBh + sb_ + so0, pB0h + (k0_)); \
    cp_async16(uBh + sb_ + so1, pB1h + (k0_)); \
    cp_async16(uBl + sb_ + so0, pB0l + (k0_)); \
    cp_async16(uBl + sb_ + so1, pB1l + (k0_)); \
    CP_COMMIT(); } while (0)

    PROJ_CP(0, 0);

    const int NCH = DIM / 32;
    for (int ch = 0; ch < NCH; ch++) {
        int cur = ch & 1;
        if (ch + 1 < NCH) { PROJ_CP(cur ^ 1, (ch + 1) * 32); CP_WAIT1(); }
        else              { CP_WAIT0(); }
        __syncthreads();
        uint32_t so = (uint32_t)(cur * PROJ_STB);
#pragma unroll
        for (int ko = 0; ko < 2; ko++) {
            uint32_t ah[4][4], al[4][4], bh[4][2], bl[4][2];
#pragma unroll
            for (int mt = 0; mt < 4; mt++) {
                uint32_t off = so + (uint32_t)(((arow_a + mt * 16) * SMS + ko * 16 + aksel) * 2);
                ldsm_x4(ah[mt], uAh + off);
                ldsm_x4(al[mt], uAl + off);
            }
#pragma unroll
            for (int nt = 0; nt < 4; nt++) {
                uint32_t off = so + (uint32_t)(((brow_b + nt * 8) * SMS + ko * 16 + bksel) * 2);
                ldsm_x2(bh[nt], uBh + off);
                ldsm_x2(bl[nt], uBl + off);
            }
#pragma unroll
            for (int mt = 0; mt < 4; mt++)
#pragma unroll
                for (int nt = 0; nt < 4; nt++) {
                    mma_bf16(acc[mt][nt], ah[mt], bh[nt]);
                    mma_bf16(acc[mt][nt], ah[mt], bl[nt]);
                    mma_bf16(acc[mt][nt], al[mt], bh[nt]);
                }
        }
        __syncthreads();
    }

    const float* bias = (sec == 0) ? bk : ((sec == 1) ? bv : bq);
    __nv_bfloat16* Chi = (sec == 0) ? g_khi : ((sec == 1) ? g_vhi : g_qhi);
    __nv_bfloat16* Clo = (sec == 0) ? g_klo : ((sec == 1) ? g_vlo : g_qlo);
    int act = (sec != 1);
    int gid = lane >> 2, tig = lane & 3;

#pragma unroll
    for (int mt = 0; mt < 4; mt++) {
        int row = m0 + warp_m * 64 + mt * 16 + gid;
#pragma unroll
        for (int nt = 0; nt < 4; nt++) {
            int colg = wc + warp_n * 32 + nt * 8 + tig * 2;
            float b0 = bias[colg], b1 = bias[colg + 1];
            float v0 = acc[mt][nt][0] + b0, v1 = acc[mt][nt][1] + b1;
            float v2 = acc[mt][nt][2] + b0, v3 = acc[mt][nt][3] + b1;
            if (act) { v0 = gelu_tanh(v0); v1 = gelu_tanh(v1); v2 = gelu_tanh(v2); v3 = gelu_tanh(v3); }
            __nv_bfloat16 h0, l0, h1, l1;
            split2(v0, h0, l0); split2(v1, h1, l1);
            *(__nv_bfloat162*)(Chi + (size_t)row * DFF + colg) = __nv_bfloat162(h0, h1);
            *(__nv_bfloat162*)(Clo + (size_t)row * DFF + colg) = __nv_bfloat162(l0, l1);
            split2(v2, h0, l0); split2(v3, h1, l1);
            *(__nv_bfloat162*)(Chi + (size_t)(row + 8) * DFF + colg) = __nv_bfloat162(h0, h1);
            *(__nv_bfloat162*)(Clo + (size_t)(row + 8) * DFF + colg) = __nv_bfloat162(l0, l1);
        }
    }
}

// ================= out GEMM: BM=64, BN=64, 256 CTAs, direct write =================
#define OUT_AS (64 * SMS)
#define OUT_ASTB (OUT_AS * 2)
#define OUT_SMEM (8 * OUT_AS * 2)
__global__ void __launch_bounds__(256) out_mma_kernel(float* __restrict__ outp)
{
    extern __shared__ __nv_bfloat16 smp[];
    __nv_bfloat16* sAh = smp;
    __nv_bfloat16* sAl = smp + 2 * OUT_AS;
    __nv_bfloat16* sBh = smp + 4 * OUT_AS;
    __nv_bfloat16* sBl = smp + 6 * OUT_AS;

    int t = threadIdx.x, wid = t >> 5, lane = t & 31;
    int warp_m = wid & 1, warp_n = wid >> 1;   // 2 x 4; warp tile 32x16
    int m0 = blockIdx.y * 64;
    int n0 = blockIdx.x * 64;

    float acc[2][2][4];
#pragma unroll
    for (int i = 0; i < 2; i++)
#pragma unroll
        for (int j = 0; j < 2; j++)
#pragma unroll
            for (int e = 0; e < 4; e++) acc[i][j][e] = 0.f;

    uint32_t uAh = smem_u32(sAh), uAl = smem_u32(sAl);
    uint32_t uBh = smem_u32(sBh), uBl = smem_u32(sBl);

    int ldrow = t >> 2, ldq = t & 3;
    uint32_t so0 = (uint32_t)((ldrow * SMS + ldq * 8) * 2);
    const __nv_bfloat16* pAh = g_yhi  + (size_t)(m0 + ldrow) * YW + ldq * 8;
    const __nv_bfloat16* pAl = g_ylo  + (size_t)(m0 + ldrow) * YW + ldq * 8;
    const __nv_bfloat16* pBh = g_wohi + (size_t)(n0 + ldrow) * YW + ldq * 8;
    const __nv_bfloat16* pBl = g_wolo + (size_t)(n0 + ldrow) * YW + ldq * 8;

    int arow_a = warp_m * 32 + (lane & 15);
    int aksel  = (lane >> 4) * 8;
    int brow_b = warp_n * 16 + (lane & 7);
    int bksel  = ((lane >> 3) & 1) * 8;

#define OUT_CP(st_, k0_) do { \
    uint32_t sb_ = (uint32_t)(st_) * OUT_ASTB; \
    cp_async16(uAh + sb_ + so0, pAh + (k0_)); \
    cp_async16(uAl + sb_ + so0, pAl + (k0_)); \
    cp_async16(uBh + sb_ + so0, pBh + (k0_)); \
    cp_async16(uBl + sb_ + so0, pBl + (k0_)); \
    CP_COMMIT(); } while (0)

    OUT_CP(0, 0);

    const int NCH = YW / 32;   // 32
    for (int ch = 0; ch < NCH; ch++) {
        int cur = ch & 1;
        if (ch + 1 < NCH) { OUT_CP(cur ^ 1, (ch + 1) * 32); CP_WAIT1(); }
        else              { CP_WAIT0(); }
        __syncthreads();
        uint32_t so = (uint32_t)(cur * OUT_ASTB);
#pragma unroll
        for (int ko = 0; ko < 2; ko++) {
            uint32_t ah[2][4], al[2][4], bh[2][2], bl[2][2];
#pragma unroll
            for (int mt = 0; mt < 2; mt++) {
                uint32_t off = so + (uint32_t)(((arow_a + mt * 16) * SMS + ko * 16 + aksel) * 2);
                ldsm_x4(ah[mt], uAh + off);
                ldsm_x4(al[mt], uAl + off);
            }
#pragma unroll
            for (int nt = 0; nt < 2; nt++) {
                uint32_t off = so + (uint32_t)(((brow_b + nt * 8) * SMS + ko * 16 + bksel) * 2);
                ldsm_x2(bh[nt], uBh + off);
                ldsm_x2(bl[nt], uBl + off);
            }
#pragma unroll
            for (int mt = 0; mt < 2; mt++)
#pragma unroll
                for (int nt = 0; nt < 2; nt++) {
                    mma_bf16(acc[mt][nt], ah[mt], bh[nt]);
                    mma_bf16(acc[mt][nt], ah[mt], bl[nt]);
                    mma_bf16(acc[mt][nt], al[mt], bh[nt]);
                }
        }
        __syncthreads();
    }

    int gid = lane >> 2, tig = lane & 3;
#pragma unroll
    for (int mt = 0; mt < 2; mt++) {
        int row = m0 + warp_m * 32 + mt * 16 + gid;
#pragma unroll
        for (int nt = 0; nt < 2; nt++) {
            int col = n0 + warp_n * 16 + nt * 8 + tig * 2;
            *(float2*)(outp + (size_t)row * DIM + col) =
                make_float2(acc[mt][nt][0], acc[mt][nt][1]);
            *(float2*)(outp + (size_t)(row + 8) * DIM + col) =
                make_float2(acc[mt][nt][2], acc[mt][nt][3]);
        }
    }
}

// ================= seg launch A: chains first [0,512), then batch p1 chunks =================
__global__ void __launch_bounds__(256) seg_a_kernel(const int* __restrict__ batchv)
{
    int bid = blockIdx.x;
    int t = threadIdx.x, wid = t >> 5, lane = t & 31;
    int wm = wid & 1, wn = wid >> 1;

    __shared__ __align__(16) __nv_bfloat16 sKh[64 * KVS];
    __shared__ __align__(16) __nv_bfloat16 sKl[64 * KVS];
    __shared__ __align__(16) __nv_bfloat16 sVh[64 * KVS];
    __shared__ __align__(16) __nv_bfloat16 sVl[64 * KVS];
    uint32_t uKh = smem_u32(sKh), uKl = smem_u32(sKl);
    uint32_t uVh = smem_u32(sVh), uVl = smem_u32(sVl);

    int mem = t >> 2, part = t & 3;
    int g = lane >> 2, tq = lane & 3;
    const uint4 Z4 = make_uint4(0, 0, 0, 0);

    int a_moff = ((lane >> 4) & 1) * 8 + (lane & 7);
    int a_coff = ((lane >> 3) & 1) * 8;
    int b_moff = lane & 15;
    int q_arow = wm * 32 + (lane & 15);
    int q_aksel = (lane >> 4) * 8;
    int a_brow = wn * 16 + (lane & 7);
    int a_bksel = ((lane >> 3) & 1) * 8;

    if (bid >= NCHAIN * NHEAD) {
        // ---- batch phase-1 chunk block ----
        int idx = bid - NCHAIN * NHEAD;
        int kz = idx >> 6;
        int s  = (idx >> 3) & 7;
        int h  = idx & 7;
        const int* L = g_list_batch + s * BA_STRIDE;
        int n = g_cnt_batch[s];
        if (kz * 64 >= n) return;

        int mrow = kz * 64 + mem;
        uint4 kh0 = Z4, kh1 = Z4, kl0 = Z4, kl1 = Z4;
        uint4 vh0 = Z4, vh1 = Z4, vl0 = Z4, vl1 = Z4;
        if (mrow < n) {
            int e = L[mrow];
            int i = e & 0x7fffffff;
            size_t base = (size_t)i * DFF + h * DHEAD + part * 16;
            if (e < 0) {
                kh0 = ((const uint4*)(g_khi + base))[0];
                kh1 = ((const uint4*)(g_khi + base))[1];
                kl0 = ((const uint4*)(g_klo + base))[0];
                kl1 = ((const uint4*)(g_klo + base))[1];
            }
            vh0 = ((const uint4*)(g_vhi + base))[0];
            vh1 = ((const uint4*)(g_vhi + base))[1];
            vl0 = ((const uint4*)(g_vlo + base))[0];
            vl1 = ((const uint4*)(g_vlo + base))[1];
        }
        int sof = mem * KVS + part * 16;
        *(uint4*)(sKh + sof) = kh0; *(uint4*)(sKh + sof + 8) = kh1;
        *(uint4*)(sKl + sof) = kl0; *(uint4*)(sKl + sof + 8) = kl1;
        *(uint4*)(sVh + sof) = vh0; *(uint4*)(sVh + sof + 8) = vh1;
        *(uint4*)(sVl + sof) = vl0; *(uint4*)(sVl + sof + 8) = vl1;
        __syncthreads();

        float acc[2][2][4];
#pragma unroll
        for (int i = 0; i < 2; i++)
#pragma unroll
            for (int j = 0; j < 2; j++)
#pragma unroll
                for (int e = 0; e < 4; e++) acc[i][j][e] = 0.f;

#pragma unroll
        for (int ks = 0; ks < 4; ks++) {
            int kb = ks * 16;
            uint32_t ah[2][4], al[2][4], bh[2][2], bl[2][2];
#pragma unroll
            for (int i = 0; i < 2; i++) {
                uint32_t off = (uint32_t)(((kb + a_moff) * KVS + wm * 32 + i * 16 + a_coff) * 2);
                ldsm_x4_t(ah[i], uKh + off);
                ldsm_x4_t(al[i], uKl + off);
            }
#pragma unroll
            for (int j = 0; j < 2; j++) {
                uint32_t off = (uint32_t)(((kb + b_moff) * KVS + wn * 16 + j * 8) * 2);
                ldsm_x2_t(bh[j], uVh + off);
                ldsm_x2_t(bl[j], uVl + off);
            }
#pragma unroll
            for (int i = 0; i < 2; i++)
#pragma unroll
                for (int j = 0; j < 2; j++) {
                    mma_bf16(acc[i][j], ah[i], bh[j]);
                    mma_bf16(acc[i][j], ah[i], bl[j]);
                    mma_bf16(acc[i][j], al[i], bh[j]);
                }
        }

        float* P = g_Apart + (size_t)idx * 4096;
#pragma unroll
        for (int i = 0; i < 2; i++) {
            int a_r = wm * 32 + i * 16 + g;
#pragma unroll
            for (int j = 0; j < 2; j++) {
                int b_c = wn * 16 + j * 8 + tq * 2;
                *(float2*)(P + a_r * 64 + b_c)       = make_float2(acc[i][j][0], acc[i][j][1]);
                *(float2*)(P + (a_r + 8) * 64 + b_c) = make_float2(acc[i][j][2], acc[i][j][3]);
            }
        }
        return;
    }

    // ---- chain full block ----
    int c = bid >> 3;
    int h = bid & 7;
    const int* L = g_list_chain + c * CH_STRIDE;
    int n = g_cnt_chain[c];
    float inv = g_minv_chain[c];
    int nchunks = (n + 63) >> 6;

    float acc[2][2][4];
#pragma unroll
    for (int i = 0; i < 2; i++)
#pragma unroll
        for (int j = 0; j < 2; j++)
#pragma unroll
            for (int e = 0; e < 4; e++) acc[i][j][e] = 0.f;

    for (int ch = 0; ch < nchunks; ch++) {
        int mrow = ch * 64 + mem;
        uint4 kh0 = Z4, kh1 = Z4, kl0 = Z4, kl1 = Z4;
        uint4 vh0 = Z4, vh1 = Z4, vl0 = Z4, vl1 = Z4;
        if (mrow < n) {
            int e = L[mrow];
            int i = e & 0x7fffffff;
            size_t base = (size_t)i * DFF + h * DHEAD + part * 16;
            if (e < 0) {
                kh0 = ((const uint4*)(g_khi + base))[0];
                kh1 = ((const uint4*)(g_khi + base))[1];
                kl0 = ((const uint4*)(g_klo + base))[0];
                kl1 = ((const uint4*)(g_klo + base))[1];
            }
            vh0 = ((const uint4*)(g_vhi + base))[0];
            vh1 = ((const uint4*)(g_vhi + base))[1];
            vl0 = ((const uint4*)(g_vlo + base))[0];
            vl1 = ((const uint4*)(g_vlo + base))[1];
        }
        int sof = mem * KVS + part * 16;
        *(uint4*)(sKh + sof) = kh0; *(uint4*)(sKh + sof + 8) = kh1;
        *(uint4*)(sKl + sof) = kl0; *(uint4*)(sKl + sof + 8) = kl1;
        *(uint4*)(sVh + sof) = vh0; *(uint4*)(sVh + sof + 8) = vh1;
        *(uint4*)(sVl + sof) = vl0; *(uint4*)(sVl + sof + 8) = vl1;
        __syncthreads();

#pragma unroll
        for (int ks = 0; ks < 4; ks++) {
            int kb = ks * 16;
            uint32_t ah[2][4], al[2][4], bh[2][2], bl[2][2];
#pragma unroll
            for (int i = 0; i < 2; i++) {
                uint32_t off = (uint32_t)(((kb + a_moff) * KVS + wm * 32 + i * 16 + a_coff) * 2);
                ldsm_x4_t(ah[i], uKh + off);
                ldsm_x4_t(al[i], uKl + off);
            }
#pragma unroll
            for (int j = 0; j < 2; j++) {
                uint32_t off = (uint32_t)(((kb + b_moff) * KVS + wn * 16 + j * 8) * 2);
                ldsm_x2_t(bh[j], uVh + off);
                ldsm_x2_t(bl[j], uVl + off);
            }
#pragma unroll
            for (int i = 0; i < 2; i++)
#pragma unroll
                for (int j = 0; j < 2; j++) {
                    mma_bf16(acc[i][j], ah[i], bh[j]);
                    mma_bf16(acc[i][j], ah[i], bl[j]);
                    mma_bf16(acc[i][j], al[i], bh[j]);
                }
        }
        __syncthreads();
    }

#pragma unroll
    for (int i = 0; i < 2; i++) {
        int a_r = wm * 32 + i * 16 + g;
#pragma unroll
        for (int j = 0; j < 2; j++) {
            int b_c = wn * 16 + j * 8 + tq * 2;
            __nv_bfloat16 h0, l0, h1, l1;
            split2(acc[i][j][0] * inv, h0, l0);
            split2(acc[i][j][1] * inv, h1, l1);
            *(__nv_bfloat162*)(sVh + a_r * KVS + b_c) = __nv_bfloat162(h0, h1);
            *(__nv_bfloat162*)(sVl + a_r * KVS + b_c) = __nv_bfloat162(l0, l1);
            split2(acc[i][j][2] * inv, h0, l0);
            split2(acc[i][j][3] * inv, h1, l1);
            *(__nv_bfloat162*)(sVh + (a_r + 8) * KVS + b_c) = __nv_bfloat162(h0, h1);
            *(__nv_bfloat162*)(sVl + (a_r + 8) * KVS + b_c) = __nv_bfloat162(l0, l1);
        }
    }
    __syncthreads();

    for (int ch = 0; ch < nchunks; ch++) {
        int mrow = ch * 64 + mem;
        uint4 qh0 = Z4, qh1 = Z4, ql0 = Z4, ql1 = Z4;
        if (mrow < n) {
            int i = L[mrow] & 0x7fffffff;
            size_t base = (size_t)i * DFF + h * DHEAD + part * 16;
            qh0 = ((const uint4*)(g_qhi + base))[0];
            qh1 = ((const uint4*)(g_qhi + base))[1];
            ql0 = ((const uint4*)(g_qlo + base))[0];
            ql1 = ((const uint4*)(g_qlo + base))[1];
        }
        int sof = mem * KVS + part * 16;
        *(uint4*)(sKh + sof) = qh0; *(uint4*)(sKh + sof + 8) = qh1;
        *(uint4*)(sKl + sof) = ql0; *(uint4*)(sKl + sof + 8) = ql1;
        __syncthreads();

        float acc2[2][2][4];
#pragma unroll
        for (int i = 0; i < 2; i++)
#pragma unroll
            for (int j = 0; j < 2; j++)
#pragma unroll
                for (int e = 0; e < 4; e++) acc2[i][j][e] = 0.f;

#pragma unroll
        for (int ks = 0; ks < 4; ks++) {
            int kb = ks * 16;
            uint32_t ah[2][4], al[2][4], bh[2][2], bl[2][2];
#pragma unroll
            for (int i = 0; i < 2; i++) {
                uint32_t off = (uint32_t)(((q_arow + i * 16) * KVS + kb + q_aksel) * 2);
                ldsm_x4(ah[i], uKh + off);
                ldsm_x4(al[i], uKl + off);
            }
#pragma unroll
            for (int j = 0; j < 2; j++) {
                uint32_t off = (uint32_t)(((a_brow + j * 8) * KVS + kb + a_bksel) * 2);
                ldsm_x2(bh[j], uVh + off);
                ldsm_x2(bl[j], uVl + off);
            }
#pragma unroll
            for (int i = 0; i < 2; i++)
#pragma unroll
                for (int j = 0; j < 2; j++) {
                    mma_bf16(acc2[i][j], ah[i], bh[j]);
                    mma_bf16(acc2[i][j], ah[i], bl[j]);
                    mma_bf16(acc2[i][j], al[i], bh[j]);
                }
        }

#pragma unroll
        for (int i = 0; i < 2; i++) {
            int mr0 = ch * 64 + wm * 32 + i * 16 + g;
#pragma unroll
            for (int j = 0; j < 2; j++) {
                int aa = wn * 16 + j * 8 + tq * 2;
                int colg = h * 128 + aa;
#pragma unroll
                for (int rr = 0; rr < 2; rr++) {
                    int mr = mr0 + rr * 8;
                    if (mr < n) {
                        int irow = L[mr] & 0x7fffffff;
                        int bb = batchv[irow];
                        float2 bm = *(const float2*)(g_bmean + (size_t)bb * YW + colg);
                        float v0 = acc2[i][j][rr * 2 + 0] + bm.x;
                        float v1 = acc2[i][j][rr * 2 + 1] + bm.y;
                        __nv_bfloat16 h0, l0, h1, l1;
                        split2(v0, h0, l0);
                        split2(v1, h1, l1);
                        *(__nv_bfloat162*)(g_yhi + (size_t)irow * YW + colg) = __nv_bfloat162(h0, h1);
                        *(__nv_bfloat162*)(g_ylo + (size_t)irow * YW + colg) = __nv_bfloat162(l0, l1);
                    }
                }
            }
        }
        __syncthreads();
    }
}

// ================= seg reduce: 512 blocks, float4/thread, dual accum chains =================
__global__ void __launch_bounds__(256) seg_red_kernel()
{
    int bid = blockIdx.x;
    int sh = bid >> 3, grp = bid & 7;
    int s = sh >> 3;
    int n = g_cnt_batch[s];
    float inv = g_minv_batch[s];
    int nch = (n + 63) >> 6;
    if (nch > KZ) nch = KZ;
    int e = grp * 512 + (threadIdx.x & 127) * 4;
    if (threadIdx.x >= 128) return;
    const float* P = g_Apart + (size_t)sh * 4096 + e;
    const size_t ZS = (size_t)64 * 4096;
    float4 a0 = make_float4(0.f, 0.f, 0.f, 0.f);
    float4 a1 = make_float4(0.f, 0.f, 0.f, 0.f);
    int z = 0;
    for (; z + 1 < nch; z += 2) {
        float4 p0 = *(const float4*)(P + (size_t)z * ZS);
        float4 p1 = *(const float4*)(P + (size_t)(z + 1) * ZS);
        a0.x += p0.x; a0.y += p0.y; a0.z += p0.z; a0.w += p0.w;
        a1.x += p1.x; a1.y += p1.y; a1.z += p1.z; a1.w += p1.w;
    }
    if (z < nch) {
        float4 p0 = *(const float4*)(P + (size_t)z * ZS);
        a0.x += p0.x; a0.y += p0.y; a0.z += p0.z; a0.w += p0.w;
    }
    float v0 = (a0.x + a1.x) * inv;
    float v1 = (a0.y + a1.y) * inv;
    float v2 = (a0.z + a1.z) * inv;
    float v3 = (a0.w + a1.w) * inv;
    __nv_bfloat16 h0, l0, h1, l1, h2, l2, h3, l3;
    split2(v0, h0, l0); split2(v1, h1, l1);
    split2(v2, h2, l2); split2(v3, h3, l3);
    *(__nv_bfloat162*)(g_Ahi + (size_t)sh * 4096 + e)     = __nv_bfloat162(h0, h1);
    *(__nv_bfloat162*)(g_Ahi + (size_t)sh * 4096 + e + 2) = __nv_bfloat162(h2, h3);
    *(__nv_bfloat162*)(g_Alo + (size_t)sh * 4096 + e)     = __nv_bfloat162(l0, l1);
    *(__nv_bfloat162*)(g_Alo + (size_t)sh * 4096 + e + 2) = __nv_bfloat162(l2, l3);
}

// ================= seg launch B: batch phase-2 chunk blocks =================
__global__ void __launch_bounds__(256) seg_b_kernel(const int* __restrict__ batchv)
{
    int bid = blockIdx.x;
    int kz = bid >> 6;
    int s  = (bid >> 3) & 7;
    int h  = bid & 7;
    int sh = s * 8 + h;
    const int* L = g_list_batch + s * BA_STRIDE;
    int n = g_cnt_batch[s];
    if (kz * 64 >= n) return;

    int t = threadIdx.x, wid = t >> 5, lane = t & 31;
    int wm = wid & 1, wn = wid >> 1;

    __shared__ __align__(16) __nv_bfloat16 sKh[64 * KVS];
    __shared__ __align__(16) __nv_bfloat16 sKl[64 * KVS];
    __shared__ __align__(16) __nv_bfloat16 sVh[64 * KVS];
    __shared__ __align__(16) __nv_bfloat16 sVl[64 * KVS];
    uint32_t uKh = smem_u32(sKh), uKl = smem_u32(sKl);
    uint32_t uVh = smem_u32(sVh), uVl = smem_u32(sVl);

    int mem = t >> 2, part = t & 3;
    int g = lane >> 2, tq = lane & 3;
    const uint4 Z4 = make_uint4(0, 0, 0, 0);

#pragma unroll
    for (int it = 0; it < 2; it++) {
        int idx = (it * 256 + t) * 8;
        int r = idx >> 6, c = idx & 63;
        *(uint4*)(sVh + r * KVS + c) = *(const uint4*)(g_Ahi + (size_t)sh * 4096 + idx);
        *(uint4*)(sVl + r * KVS + c) = *(const uint4*)(g_Alo + (size_t)sh * 4096 + idx);
    }
    int mrow = kz * 64 + mem;
    uint4 qh0 = Z4, qh1 = Z4, ql0 = Z4, ql1 = Z4;
    if (mrow < n) {
        int i = L[mrow] & 0x7fffffff;
        size_t base = (size_t)i * DFF + h * DHEAD + part * 16;
        qh0 = ((const uint4*)(g_qhi + base))[0];
        qh1 = ((const uint4*)(g_qhi + base))[1];
        ql0 = ((const uint4*)(g_qlo + base))[0];
        ql1 = ((const uint4*)(g_qlo + base))[1];
    }
    int sof = mem * KVS + part * 16;
    *(uint4*)(sKh + sof) = qh0; *(uint4*)(sKh + sof + 8) = qh1;
    *(uint4*)(sKl + sof) = ql0; *(uint4*)(sKl + sof + 8) = ql1;
    __syncthreads();

    int q_arow = wm * 32 + (lane & 15);
    int q_aksel = (lane >> 4) * 8;
    int a_brow = wn * 16 + (lane & 7);
    int a_bksel = ((lane >> 3) & 1) * 8;

    float acc2[2][2][4];
#pragma unroll
    for (int i = 0; i < 2; i++)
#pragma unroll
        for (int j = 0; j < 2; j++)
#pragma unroll
            for (int e = 0; e < 4; e++) acc2[i][j][e] = 0.f;

#pragma unroll
    for (int ks = 0; ks < 4; ks++) {
        int kb = ks * 16;
        uint32_t ah[2][4], al[2][4], bh[2][2], bl[2][2];
#pragma unroll
        for (int i = 0; i < 2; i++) {
            uint32_t off = (uint32_t)(((q_arow + i * 16) * KVS + kb + q_aksel) * 2);
            ldsm_x4(ah[i], uKh + off);
            ldsm_x4(al[i], uKl + off);
        }
#pragma unroll
        for (int j = 0; j < 2; j++) {
            uint32_t off = (uint32_t)(((a_brow + j * 8) * KVS + kb + a_bksel) * 2);
            ldsm_x2(bh[j], uVh + off);
            ldsm_x2(bl[j], uVl + off);
        }
#pragma unroll
        for (int i = 0; i < 2; i++)
#pragma unroll
            for (int j = 0; j < 2; j++) {
                mma_bf16(acc2[i][j], ah[i], bh[j]);
                mma_bf16(acc2[i][j], ah[i], bl[j]);
                mma_bf16(acc2[i][j], al[i], bh[j]);
            }
    }

#pragma unroll
    for (int i = 0; i < 2; i++) {
        int mr0 = kz * 64 + wm * 32 + i * 16 + g;
#pragma unroll
        for (int j = 0; j < 2; j++) {
            int aa = wn * 16 + j * 8 + tq * 2;
            int colg = h * 128 + DHEAD + aa;
#pragma unroll
            for (int rr = 0; rr < 2; rr++) {
                int mr = mr0 + rr * 8;
                if (mr < n) {
                    int irow = L[mr] & 0x7fffffff;
                    int bb = batchv[irow];
                    float2 bm = *(const float2*)(g_bmean + (size_t)bb * YW + colg);
                    float v0 = acc2[i][j][rr * 2 + 0] + bm.x;
                    float v1 = acc2[i][j][rr * 2 + 1] + bm.y;
                    __nv_bfloat16 h0, l0, h1, l1;
                    split2(v0, h0, l0);
                    split2(v1, h1, l1);
                    *(__nv_bfloat162*)(g_yhi + (size_t)irow * YW + colg) = __nv_bfloat162(h0, h1);
                    *(__nv_bfloat162*)(g_ylo + (size_t)irow * YW + colg) = __nv_bfloat162(l0, l1);
                }
            }
        }
    }
}

// ================= launch =================
extern "C" void kernel_launch(void* const* d_in, const int* in_sizes, int n_in,
                              void* d_out, int out_size)
{
    const float* local   = (const float*)d_in[0];
    const int*   chain   = (const int*)  d_in[1];
    const int*   batch   = (const int*)  d_in[2];
    const void*  mask    = d_in[3];
    const float* W_key   = (const float*)d_in[4];
    const float* b_key   = (const float*)d_in[5];
    const float* W_value = (const float*)d_in[6];
    const float* b_value = (const float*)d_in[7];
    const float* W_query = (const float*)d_in[8];
    const float* b_query = (const float*)d_in[9];
    const float* W_bias  = (const float*)d_in[10];
    const float* b_bias  = (const float*)d_in[11];
    const float* W_out   = (const float*)d_in[12];
    float* out = (float*)d_out;

    static bool attr_done = false;
    if (!attr_done) {
        cudaFuncSetAttribute(proj_mma_kernel, cudaFuncAttributeMaxDynamicSharedMemorySize, PROJ_SMEM);
        cudaFuncSetAttribute(out_mma_kernel,  cudaFuncAttributeMaxDynamicSharedMemorySize, OUT_SMEM);
        attr_done = true;
    }

    build_all_kernel<<<NBATCH + NCHAIN, 1024>>>(chain, batch, mask, local, W_bias, b_bias);

    prep_kernel<<<3072, 256>>>(local, W_key, W_value, W_query, W_out);

    proj_mma_kernel<<<dim3(1536 / 128, NROWS / 128), 256, PROJ_SMEM>>>(b_key, b_value, b_query);

    seg_a_kernel<<<NCHAIN * NHEAD + KZ * NBATCH * NHEAD, 256>>>(batch);
    seg_red_kernel<<<NBATCH * NHEAD * 8, 256>>>();
    seg_b_kernel<<<KZ * NBATCH * NHEAD, 256>>>(batch);

    out_mma_kernel<<<dim3(DIM / 64, NROWS / 64), 256, OUT_SMEM>>>(out);
}

// round 17
// speedup vs baseline: 1.1636x; 1.1636x over previous
#include <cuda_runtime.h>
#include <cuda_bf16.h>
#include <cstdint>

#define NROWS 4096
#define DIM 256
#define DFF 512
#define NHEAD 8
#define DHEAD 64
#define NCHAIN 64
#define NBATCH 8
#define YW 1024
#define CH_STRIDE 256
#define BA_STRIDE 1024
#define KZ 12

// ================= mma.sync / cp.async helpers =================
__device__ __forceinline__ uint32_t smem_u32(const void* p) {
    uint32_t a;
    asm("{ .reg .u64 t; cvta.to.shared.u64 t, %1; cvt.u32.u64 %0, t; }" : "=r"(a) : "l"(p));
    return a;
}
__device__ __forceinline__ void mma_bf16(float* c, const uint32_t* a, const uint32_t* b) {
    asm volatile(
        "mma.sync.aligned.m16n8k16.row.col.f32.bf16.bf16.f32 "
        "{%0,%1,%2,%3}, {%4,%5,%6,%7}, {%8,%9}, {%0,%1,%2,%3};"
        : "+f"(c[0]), "+f"(c[1]), "+f"(c[2]), "+f"(c[3])
        : "r"(a[0]), "r"(a[1]), "r"(a[2]), "r"(a[3]), "r"(b[0]), "r"(b[1]));
}
__device__ __forceinline__ void ldsm_x4(uint32_t* r, uint32_t addr) {
    asm volatile("ldmatrix.sync.aligned.m8n8.x4.shared.b16 {%0,%1,%2,%3}, [%4];"
                 : "=r"(r[0]), "=r"(r[1]), "=r"(r[2]), "=r"(r[3]) : "r"(addr));
}
__device__ __forceinline__ void ldsm_x2(uint32_t* r, uint32_t addr) {
    asm volatile("ldmatrix.sync.aligned.m8n8.x2.shared.b16 {%0,%1}, [%2];"
                 : "=r"(r[0]), "=r"(r[1]) : "r"(addr));
}
__device__ __forceinline__ void ldsm_x4_t(uint32_t* r, uint32_t addr) {
    asm volatile("ldmatrix.sync.aligned.m8n8.x4.trans.shared.b16 {%0,%1,%2,%3}, [%4];"
                 : "=r"(r[0]), "=r"(r[1]), "=r"(r[2]), "=r"(r[3]) : "r"(addr));
}
__device__ __forceinline__ void ldsm_x2_t(uint32_t* r, uint32_t addr) {
    asm volatile("ldmatrix.sync.aligned.m8n8.x2.trans.shared.b16 {%0,%1}, [%2];"
                 : "=r"(r[0]), "=r"(r[1]) : "r"(addr));
}
__device__ __forceinline__ void cp_async16(uint32_t saddr, const void* g) {
    asm volatile("cp.async.cg.shared.global [%0], [%1], 16;" :: "r"(saddr), "l"(g));
}
#define CP_COMMIT() asm volatile("cp.async.commit_group;" ::: "memory")
#define CP_WAIT1()  asm volatile("cp.async.wait_group 1;" ::: "memory")
#define CP_WAIT0()  asm volatile("cp.async.wait_group 0;" ::: "memory")

#define SMS 40
#define KVS 72

// ================= scratch =================
__device__ float g_bmean[NBATCH * YW];
__device__ float g_Apart[KZ * NBATCH * NHEAD * 4096];
__device__ __nv_bfloat16 g_Ahi[NBATCH * NHEAD * 4096];
__device__ __nv_bfloat16 g_Alo[NBATCH * NHEAD * 4096];

__device__ __nv_bfloat16 g_khi[NROWS * DFF];
__device__ __nv_bfloat16 g_klo[NROWS * DFF];
__device__ __nv_bfloat16 g_vhi[NROWS * DFF];
__device__ __nv_bfloat16 g_vlo[NROWS * DFF];
__device__ __nv_bfloat16 g_qhi[NROWS * DFF];
__device__ __nv_bfloat16 g_qlo[NROWS * DFF];

__device__ __nv_bfloat16 g_lhi[NROWS * DIM];
__device__ __nv_bfloat16 g_llo[NROWS * DIM];
__device__ __nv_bfloat16 g_wthi[3 * DFF * DIM];
__device__ __nv_bfloat16 g_wtlo[3 * DFF * DIM];
__device__ __nv_bfloat16 g_yhi[NROWS * YW];
__device__ __nv_bfloat16 g_ylo[NROWS * YW];
__device__ __nv_bfloat16 g_wohi[DIM * YW];
__device__ __nv_bfloat16 g_wolo[DIM * YW];

__device__ int   g_list_chain[NCHAIN * CH_STRIDE];
__device__ int   g_list_batch[NBATCH * BA_STRIDE];
__device__ int   g_cnt_chain[NCHAIN];
__device__ int   g_cnt_batch[NBATCH];
__device__ float g_minv_chain[NCHAIN];
__device__ float g_minv_batch[NBATCH];

// ================= fused: mask-mode detect + list build + batch xsum + bmean =================
__global__ void __launch_bounds__(1024) build_all_kernel(
    const int* __restrict__ chain, const int* __restrict__ batch,
    const void* __restrict__ maskp,
    const float* __restrict__ local,
    const float* __restrict__ W_bias, const float* __restrict__ b_bias)
{
    int blk = blockIdx.x;
    bool isb = (blk < NBATCH);
    int s = isb ? blk : blk - NBATCH;
    const int* seg = isb ? batch : chain;
    int stride = isb ? BA_STRIDE : CH_STRIDE;
    int* list = isb ? g_list_batch : g_list_chain;
    int* cnts = isb ? g_cnt_batch : g_cnt_chain;
    float* minv = isb ? g_minv_batch : g_minv_chain;
    const unsigned char* mb = (const unsigned char*)maskp;
    const unsigned int*  mw = (const unsigned int*)maskp;

    int t = threadIdx.x;
    int w = t >> 5, lane = t & 31;
    __shared__ int woff[32];
    __shared__ int wred[32];
    __shared__ int sbase, snext;
    __shared__ int smode;
    __shared__ float sinv;
    __shared__ float xs4[4][DIM];
    __shared__ float xs[DIM];

    {
        int c = 0;
#pragma unroll
        for (int r = 0; r < NROWS / 1024; r++) c += (mb[r * 1024 + t] != 0);
        for (int o = 16; o > 0; o >>= 1) c += __shfl_down_sync(0xffffffffu, c, o);
        if (lane == 0) wred[w] = c;
        __syncthreads();
        if (w == 0) {
            int v = wred[lane];
            for (int o = 16; o > 0; o >>= 1) v += __shfl_down_sync(0xffffffffu, v, o);
            if (lane == 0) smode = (2 * v > NROWS) ? 1 : 0;
        }
    }
    if (t == 0) sbase = 0;
    int mcount = 0;
    __syncthreads();
    int mode = smode;

    for (int c = 0; c < NROWS / 1024; c++) {
        int i = c * 1024 + t;
        bool pred = (seg[i] == s);
        bool on = mode ? (mb[i] != 0) : (mw[i] != 0u);
        bool mk = pred && on;
        unsigned ball = __ballot_sync(0xffffffffu, pred);
        int wpre = __popc(ball & ((1u << lane) - 1u));
        if (lane == 0) woff[w] = __popc(ball);
        __syncthreads();
        if (w == 0) {
            int v = woff[lane];
            int sc = v;
            for (int o = 1; o < 32; o <<= 1) {
                int nb = __shfl_up_sync(0xffffffffu, sc, o);
                if (lane >= o) sc += nb;
            }
            woff[lane] = sbase + sc - v;
            if (lane == 31) snext = sbase + sc;
        }
        __syncthreads();
        if (pred) list[s * stride + woff[w] + wpre] = i | (mk ? 0x80000000 : 0);
        mcount += mk ? 1 : 0;
        if (t == 0) sbase = snext;
        __syncthreads();
    }

    for (int o = 16; o > 0; o >>= 1) mcount += __shfl_down_sync(0xffffffffu, mcount, o);
    if (lane == 0) wred[w] = mcount;
    __syncthreads();
    if (w == 0) {
        int v = wred[lane];
        for (int o = 16; o > 0; o >>= 1) v += __shfl_down_sync(0xffffffffu, v, o);
        if (lane == 0) {
            cnts[s] = sbase;
            float iv = 1.0f / fmaxf((float)v, 1e-6f);
            minv[s] = iv;
            sinv = iv;
        }
    }
    __syncthreads();

    if (!isb) return;

    int n = sbase;
    int quarter = t >> 8, col = t & 255;
    float a = 0.f;
    const int* L = list + s * stride;
    for (int m = quarter; m < n; m += 4) {
        int e = L[m];
        if (e < 0) a += local[(size_t)(e & 0x7fffffff) * DIM + col];
    }
    xs4[quarter][col] = a;
    __syncthreads();
    if (t < DIM) xs[t] = (xs4[0][t] + xs4[1][t]) + (xs4[2][t] + xs4[3][t]);
    __syncthreads();

    float inv = sinv;
    float acc = 0.f;
#pragma unroll 8
    for (int k = 0; k < DIM; k++) acc += xs[k] * W_bias[(size_t)k * YW + t];
    g_bmean[s * YW + t] = acc * inv + b_bias[t];
}

__device__ __forceinline__ float gelu_tanh(float x) {
    float x3 = x * x * x;
    float inner = 0.7978845608028654f * (x + 0.044715f * x3);
    return 0.5f * x * (1.0f + tanhf(inner));
}

__device__ __forceinline__ void split2(float x, __nv_bfloat16& h, __nv_bfloat16& l) {
    h = __float2bfloat16(x);
    l = __float2bfloat16(x - __bfloat162float(h));
}

// ================= fused prep =================
__global__ void prep_kernel(const float* __restrict__ X,
                            const float* __restrict__ Wk, const float* __restrict__ Wv,
                            const float* __restrict__ Wq, const float* __restrict__ Wo)
{
    int bid = blockIdx.x;
    int t = threadIdx.x;
    if (bid < 1024) {
        int i4 = (bid * 256 + t) * 4;
        float4 x = *(const float4*)(X + i4);
        __nv_bfloat16 h, l;
        split2(x.x, h, l); g_lhi[i4 + 0] = h; g_llo[i4 + 0] = l;
        split2(x.y, h, l); g_lhi[i4 + 1] = h; g_llo[i4 + 1] = l;
        split2(x.z, h, l); g_lhi[i4 + 2] = h; g_llo[i4 + 2] = l;
        split2(x.w, h, l); g_lhi[i4 + 3] = h; g_llo[i4 + 3] = l;
        return;
    }
    __shared__ float tile[32][33];
    int b = bid - 1024;
    int z = b / 512;
    int rem = b - z * 512;
    int nx0 = (rem & 15) * 32, ky0 = (rem >> 4) * 32;
    const float* W;
    int K, N, roff;
    __nv_bfloat16 *hi, *lo;
    if (z == 0)      { W = Wk; K = DIM; N = DFF; hi = g_wthi; lo = g_wtlo; roff = 0; }
    else if (z == 1) { W = Wv; K = DIM; N = DFF; hi = g_wthi; lo = g_wtlo; roff = DFF; }
    else if (z == 2) { W = Wq; K = DIM; N = DFF; hi = g_wthi; lo = g_wtlo; roff = 2 * DFF; }
    else             { W = Wo; K = YW;  N = DIM; hi = g_wohi; lo = g_wolo; roff = 0; }
    if (nx0 >= N || ky0 >= K) return;
    int tx = t & 31, ty = t >> 5;

#pragma unroll
    for (int r = 0; r < 4; r++) {
        int k = ky0 + ty + r * 8;
        tile[ty + r * 8][tx] = W[(size_t)k * N + nx0 + tx];
    }
    __syncthreads();
#pragma unroll
    for (int r = 0; r < 4; r++) {
        int n = nx0 + ty + r * 8;
        float x = tile[tx][ty + r * 8];
        __nv_bfloat16 h, l;
        split2(x, h, l);
        hi[(size_t)(roff + n) * K + ky0 + tx] = h;
        lo[(size_t)(roff + n) * K + ky0 + tx] = l;
    }
}

// ================= proj GEMM =================
#define PROJ_AS (128 * SMS)
#define PROJ_STB (PROJ_AS * 2)
#define PROJ_SMEM (8 * PROJ_AS * 2)
__global__ void __launch_bounds__(256) proj_mma_kernel(
    const float* __restrict__ bk, const float* __restrict__ bv, const float* __restrict__ bq)
{
    extern __shared__ __nv_bfloat16 smp[];
    __nv_bfloat16* sAh = smp;
    __nv_bfloat16* sAl = smp + 2 * PROJ_AS;
    __nv_bfloat16* sBh = smp + 4 * PROJ_AS;
    __nv_bfloat16* sBl = smp + 6 * PROJ_AS;

    int t = threadIdx.x, wid = t >> 5, lane = t & 31;
    int warp_m = wid & 1, warp_n = wid >> 1;
    int m0 = blockIdx.y * 128;
    int gn0 = blockIdx.x * 128;
    int sec = gn0 >> 9, wc = gn0 & 511;

    float acc[4][4][4];
#pragma unroll
    for (int i = 0; i < 4; i++)
#pragma unroll
        for (int j = 0; j < 4; j++)
#pragma unroll
            for (int e = 0; e < 4; e++) acc[i][j][e] = 0.f;

    uint32_t uAh = smem_u32(sAh), uAl = smem_u32(sAl);
    uint32_t uBh = smem_u32(sBh), uBl = smem_u32(sBl);

    int ldrow = t >> 2, ldq = t & 3;
    uint32_t so0 = (uint32_t)((ldrow * SMS + ldq * 8) * 2);
    uint32_t so1 = (uint32_t)(((ldrow + 64) * SMS + ldq * 8) * 2);
    const __nv_bfloat16* pA0h = g_lhi  + (size_t)(m0 + ldrow) * DIM + ldq * 8;
    const __nv_bfloat16* pA1h = g_lhi  + (size_t)(m0 + ldrow + 64) * DIM + ldq * 8;
    const __nv_bfloat16* pA0l = g_llo  + (size_t)(m0 + ldrow) * DIM + ldq * 8;
    const __nv_bfloat16* pA1l = g_llo  + (size_t)(m0 + ldrow + 64) * DIM + ldq * 8;
    const __nv_bfloat16* pB0h = g_wthi + (size_t)(gn0 + ldrow) * DIM + ldq * 8;
    const __nv_bfloat16* pB1h = g_wthi + (size_t)(gn0 + ldrow + 64) * DIM + ldq * 8;
    const __nv_bfloat16* pB0l = g_wtlo + (size_t)(gn0 + ldrow) * DIM + ldq * 8;
    const __nv_bfloat16* pB1l = g_wtlo + (size_t)(gn0 + ldrow + 64) * DIM + ldq * 8;

    int arow_a = warp_m * 64 + (lane & 15);
    int aksel  = (lane >> 4) * 8;
    int brow_b = warp_n * 32 + (lane & 7);
    int bksel  = ((lane >> 3) & 1) * 8;

#define PROJ_CP(st_, k0_) do { \
    uint32_t sb_ = (uint32_t)(st_) * PROJ_STB; \
    cp_async16(uAh + sb_ + so0, pA0h + (k0_)); \
    cp_async16(uAh + sb_ + so1, pA1h + (k0_)); \
    cp_async16(uAl + sb_ + so0, pA0l + (k0_)); \
    cp_async16(uAl + sb_ + so1, pA1l + (k0_)); \
    cp_async16(uBh + sb_ + so0, pB0h + (k0_)); \
    cp_async16(uBh + sb_ + so1, pB1h + (k0_)); \
    cp_async16(uBl + sb_ + so0, pB0l + (k0_)); \
    cp_async16(uBl + sb_ + so1, pB1l + (k0_)); \
    CP_COMMIT(); } while (0)

    PROJ_CP(0, 0);

    const int NCH = DIM / 32;
    for (int ch = 0; ch < NCH; ch++) {
        int cur = ch & 1;
        if (ch + 1 < NCH) { PROJ_CP(cur ^ 1, (ch + 1) * 32); CP_WAIT1(); }
        else              { CP_WAIT0(); }
        __syncthreads();
        uint32_t so = (uint32_t)(cur * PROJ_STB);
#pragma unroll
        for (int ko = 0; ko < 2; ko++) {
            uint32_t ah[4][4], al[4][4], bh[4][2], bl[4][2];
#pragma unroll
            for (int mt = 0; mt < 4; mt++) {
                uint32_t off = so + (uint32_t)(((arow_a + mt * 16) * SMS + ko * 16 + aksel) * 2);
                ldsm_x4(ah[mt], uAh + off);
                ldsm_x4(al[mt], uAl + off);
            }
#pragma unroll
            for (int nt = 0; nt < 4; nt++) {
                uint32_t off = so + (uint32_t)(((brow_b + nt * 8) * SMS + ko * 16 + bksel) * 2);
                ldsm_x2(bh[nt], uBh + off);
                ldsm_x2(bl[nt], uBl + off);
            }
#pragma unroll
            for (int mt = 0; mt < 4; mt++)
#pragma unroll
                for (int nt = 0; nt < 4; nt++) {
                    mma_bf16(acc[mt][nt], ah[mt], bh[nt]);
                    mma_bf16(acc[mt][nt], ah[mt], bl[nt]);
                    mma_bf16(acc[mt][nt], al[mt], bh[nt]);
                }
        }
        __syncthreads();
    }

    const float* bias = (sec == 0) ? bk : ((sec == 1) ? bv : bq);
    __nv_bfloat16* Chi = (sec == 0) ? g_khi : ((sec == 1) ? g_vhi : g_qhi);
    __nv_bfloat16* Clo = (sec == 0) ? g_klo : ((sec == 1) ? g_vlo : g_qlo);
    int act = (sec != 1);
    int gid = lane >> 2, tig = lane & 3;

#pragma unroll
    for (int mt = 0; mt < 4; mt++) {
        int row = m0 + warp_m * 64 + mt * 16 + gid;
#pragma unroll
        for (int nt = 0; nt < 4; nt++) {
            int colg = wc + warp_n * 32 + nt * 8 + tig * 2;
            float b0 = bias[colg], b1 = bias[colg + 1];
            float v0 = acc[mt][nt][0] + b0, v1 = acc[mt][nt][1] + b1;
            float v2 = acc[mt][nt][2] + b0, v3 = acc[mt][nt][3] + b1;
            if (act) { v0 = gelu_tanh(v0); v1 = gelu_tanh(v1); v2 = gelu_tanh(v2); v3 = gelu_tanh(v3); }
            __nv_bfloat16 h0, l0, h1, l1;
            split2(v0, h0, l0); split2(v1, h1, l1);
            *(__nv_bfloat162*)(Chi + (size_t)row * DFF + colg) = __nv_bfloat162(h0, h1);
            *(__nv_bfloat162*)(Clo + (size_t)row * DFF + colg) = __nv_bfloat162(l0, l1);
            split2(v2, h0, l0); split2(v3, h1, l1);
            *(__nv_bfloat162*)(Chi + (size_t)(row + 8) * DFF + colg) = __nv_bfloat162(h0, h1);
            *(__nv_bfloat162*)(Clo + (size_t)(row + 8) * DFF + colg) = __nv_bfloat162(l0, l1);
        }
    }
}

// ================= out GEMM (R15 proven: BM=64, BN=128, direct write) =================
#define OUT_AS (64 * SMS)
#define OUT_BS (128 * SMS)
#define OUT_ASTB (OUT_AS * 2)
#define OUT_BSTB (OUT_BS * 2)
#define OUT_SMEM ((4 * OUT_AS + 4 * OUT_BS) * 2)
__global__ void __launch_bounds__(256) out_mma_kernel(float* __restrict__ outp)
{
    extern __shared__ __nv_bfloat16 smp[];
    __nv_bfloat16* sAh = smp;
    __nv_bfloat16* sAl = smp + 2 * OUT_AS;
    __nv_bfloat16* sBh = smp + 4 * OUT_AS;
    __nv_bfloat16* sBl = smp + 4 * OUT_AS + 2 * OUT_BS;

    int t = threadIdx.x, wid = t >> 5, lane = t & 31;
    int warp_m = wid & 1, warp_n = wid >> 1;
    int m0 = blockIdx.y * 64;
    int n0 = blockIdx.x * 128;

    float acc[2][4][4];
#pragma unroll
    for (int i = 0; i < 2; i++)
#pragma unroll
        for (int j = 0; j < 4; j++)
#pragma unroll
            for (int e = 0; e < 4; e++) acc[i][j][e] = 0.f;

    uint32_t uAh = smem_u32(sAh), uAl = smem_u32(sAl);
    uint32_t uBh = smem_u32(sBh), uBl = smem_u32(sBl);

    int ldrow = t >> 2, ldq = t & 3;
    uint32_t so0 = (uint32_t)((ldrow * SMS + ldq * 8) * 2);
    uint32_t so1 = (uint32_t)(((ldrow + 64) * SMS + ldq * 8) * 2);
    const __nv_bfloat16* pAh = g_yhi  + (size_t)(m0 + ldrow) * YW + ldq * 8;
    const __nv_bfloat16* pAl = g_ylo  + (size_t)(m0 + ldrow) * YW + ldq * 8;
    const __nv_bfloat16* pB0h = g_wohi + (size_t)(n0 + ldrow) * YW + ldq * 8;
    const __nv_bfloat16* pB1h = g_wohi + (size_t)(n0 + ldrow + 64) * YW + ldq * 8;
    const __nv_bfloat16* pB0l = g_wolo + (size_t)(n0 + ldrow) * YW + ldq * 8;
    const __nv_bfloat16* pB1l = g_wolo + (size_t)(n0 + ldrow + 64) * YW + ldq * 8;

    int arow_a = warp_m * 32 + (lane & 15);
    int aksel  = (lane >> 4) * 8;
    int brow_b = warp_n * 32 + (lane & 7);
    int bksel  = ((lane >> 3) & 1) * 8;

#define OUT_CP(st_, k0_) do { \
    uint32_t sa_ = (uint32_t)(st_) * OUT_ASTB; \
    uint32_t sb_ = (uint32_t)(st_) * OUT_BSTB; \
    cp_async16(uAh + sa_ + so0, pAh + (k0_)); \
    cp_async16(uAl + sa_ + so0, pAl + (k0_)); \
    cp_async16(uBh + sb_ + so0, pB0h + (k0_)); \
    cp_async16(uBh + sb_ + so1, pB1h + (k0_)); \
    cp_async16(uBl + sb_ + so0, pB0l + (k0_)); \
    cp_async16(uBl + sb_ + so1, pB1l + (k0_)); \
    CP_COMMIT(); } while (0)

    OUT_CP(0, 0);

    const int NCH = YW / 32;
    for (int ch = 0; ch < NCH; ch++) {
        int cur = ch & 1;
        if (ch + 1 < NCH) { OUT_CP(cur ^ 1, (ch + 1) * 32); CP_WAIT1(); }
        else              { CP_WAIT0(); }
        __syncthreads();
        uint32_t soA = (uint32_t)(cur * OUT_ASTB);
        uint32_t soB = (uint32_t)(cur * OUT_BSTB);
#pragma unroll
        for (int ko = 0; ko < 2; ko++) {
            uint32_t ah[2][4], al[2][4], bh[4][2], bl[4][2];
#pragma unroll
            for (int mt = 0; mt < 2; mt++) {
                uint32_t off = soA + (uint32_t)(((arow_a + mt * 16) * SMS + ko * 16 + aksel) * 2);
                ldsm_x4(ah[mt], uAh + off);
                ldsm_x4(al[mt], uAl + off);
            }
#pragma unroll
            for (int nt = 0; nt < 4; nt++) {
                uint32_t off = soB + (uint32_t)(((brow_b + nt * 8) * SMS + ko * 16 + bksel) * 2);
                ldsm_x2(bh[nt], uBh + off);
                ldsm_x2(bl[nt], uBl + off);
            }
#pragma unroll
            for (int mt = 0; mt < 2; mt++)
#pragma unroll
                for (int nt = 0; nt < 4; nt++) {
                    mma_bf16(acc[mt][nt], ah[mt], bh[nt]);
                    mma_bf16(acc[mt][nt], ah[mt], bl[nt]);
                    mma_bf16(acc[mt][nt], al[mt], bh[nt]);
                }
        }
        __syncthreads();
    }

    int gid = lane >> 2, tig = lane & 3;
#pragma unroll
    for (int mt = 0; mt < 2; mt++) {
        int row = m0 + warp_m * 32 + mt * 16 + gid;
#pragma unroll
        for (int nt = 0; nt < 4; nt++) {
            int col = n0 + warp_n * 32 + nt * 8 + tig * 2;
            *(float2*)(outp + (size_t)row * DIM + col) =
                make_float2(acc[mt][nt][0], acc[mt][nt][1]);
            *(float2*)(outp + (size_t)(row + 8) * DIM + col) =
                make_float2(acc[mt][nt][2], acc[mt][nt][3]);
        }
    }
}

// ================= seg launch A: chains first [0,512), then batch p1 chunks =================
__global__ void __launch_bounds__(256) seg_a_kernel(const int* __restrict__ batchv)
{
    int bid = blockIdx.x;
    int t = threadIdx.x, wid = t >> 5, lane = t & 31;
    int wm = wid & 1, wn = wid >> 1;

    __shared__ __align__(16) __nv_bfloat16 sKh[64 * KVS];
    __shared__ __align__(16) __nv_bfloat16 sKl[64 * KVS];
    __shared__ __align__(16) __nv_bfloat16 sVh[64 * KVS];
    __shared__ __align__(16) __nv_bfloat16 sVl[64 * KVS];
    uint32_t uKh = smem_u32(sKh), uKl = smem_u32(sKl);
    uint32_t uVh = smem_u32(sVh), uVl = smem_u32(sVl);

    int mem = t >> 2, part = t & 3;
    int g = lane >> 2, tq = lane & 3;
    const uint4 Z4 = make_uint4(0, 0, 0, 0);

    int a_moff = ((lane >> 4) & 1) * 8 + (lane & 7);
    int a_coff = ((lane >> 3) & 1) * 8;
    int b_moff = lane & 15;
    int q_arow = wm * 32 + (lane & 15);
    int q_aksel = (lane >> 4) * 8;
    int a_brow = wn * 16 + (lane & 7);
    int a_bksel = ((lane >> 3) & 1) * 8;

    if (bid >= NCHAIN * NHEAD) {
        int idx = bid - NCHAIN * NHEAD;
        int kz = idx >> 6;
        int s  = (idx >> 3) & 7;
        int h  = idx & 7;
        const int* L = g_list_batch + s * BA_STRIDE;
        int n = g_cnt_batch[s];
        if (kz * 64 >= n) return;

        int mrow = kz * 64 + mem;
        uint4 kh0 = Z4, kh1 = Z4, kl0 = Z4, kl1 = Z4;
        uint4 vh0 = Z4, vh1 = Z4, vl0 = Z4, vl1 = Z4;
        if (mrow < n) {
            int e = L[mrow];
            int i = e & 0x7fffffff;
            size_t base = (size_t)i * DFF + h * DHEAD + part * 16;
            if (e < 0) {
                kh0 = ((const uint4*)(g_khi + base))[0];
                kh1 = ((const uint4*)(g_khi + base))[1];
                kl0 = ((const uint4*)(g_klo + base))[0];
                kl1 = ((const uint4*)(g_klo + base))[1];
            }
            vh0 = ((const uint4*)(g_vhi + base))[0];
            vh1 = ((const uint4*)(g_vhi + base))[1];
            vl0 = ((const uint4*)(g_vlo + base))[0];
            vl1 = ((const uint4*)(g_vlo + base))[1];
        }
        int sof = mem * KVS + part * 16;
        *(uint4*)(sKh + sof) = kh0; *(uint4*)(sKh + sof + 8) = kh1;
        *(uint4*)(sKl + sof) = kl0; *(uint4*)(sKl + sof + 8) = kl1;
        *(uint4*)(sVh + sof) = vh0; *(uint4*)(sVh + sof + 8) = vh1;
        *(uint4*)(sVl + sof) = vl0; *(uint4*)(sVl + sof + 8) = vl1;
        __syncthreads();

        float acc[2][2][4];
#pragma unroll
        for (int i = 0; i < 2; i++)
#pragma unroll
            for (int j = 0; j < 2; j++)
#pragma unroll
                for (int e = 0; e < 4; e++) acc[i][j][e] = 0.f;

#pragma unroll
        for (int ks = 0; ks < 4; ks++) {
            int kb = ks * 16;
            uint32_t ah[2][4], al[2][4], bh[2][2], bl[2][2];
#pragma unroll
            for (int i = 0; i < 2; i++) {
                uint32_t off = (uint32_t)(((kb + a_moff) * KVS + wm * 32 + i * 16 + a_coff) * 2);
                ldsm_x4_t(ah[i], uKh + off);
                ldsm_x4_t(al[i], uKl + off);
            }
#pragma unroll
            for (int j = 0; j < 2; j++) {
                uint32_t off = (uint32_t)(((kb + b_moff) * KVS + wn * 16 + j * 8) * 2);
                ldsm_x2_t(bh[j], uVh + off);
                ldsm_x2_t(bl[j], uVl + off);
            }
#pragma unroll
            for (int i = 0; i < 2; i++)
#pragma unroll
                for (int j = 0; j < 2; j++) {
                    mma_bf16(acc[i][j], ah[i], bh[j]);
                    mma_bf16(acc[i][j], ah[i], bl[j]);
                    mma_bf16(acc[i][j], al[i], bh[j]);
                }
        }

        float* P = g_Apart + (size_t)idx * 4096;
#pragma unroll
        for (int i = 0; i < 2; i++) {
            int a_r = wm * 32 + i * 16 + g;
#pragma unroll
            for (int j = 0; j < 2; j++) {
                int b_c = wn * 16 + j * 8 + tq * 2;
                *(float2*)(P + a_r * 64 + b_c)       = make_float2(acc[i][j][0], acc[i][j][1]);
                *(float2*)(P + (a_r + 8) * 64 + b_c) = make_float2(acc[i][j][2], acc[i][j][3]);
            }
        }
        return;
    }

    // ---- chain full block ----
    int c = bid >> 3;
    int h = bid & 7;
    const int* L = g_list_chain + c * CH_STRIDE;
    int n = g_cnt_chain[c];
    float inv = g_minv_chain[c];
    int nchunks = (n + 63) >> 6;

    float acc[2][2][4];
#pragma unroll
    for (int i = 0; i < 2; i++)
#pragma unroll
        for (int j = 0; j < 2; j++)
#pragma unroll
            for (int e = 0; e < 4; e++) acc[i][j][e] = 0.f;

    for (int ch = 0; ch < nchunks; ch++) {
        int mrow = ch * 64 + mem;
        uint4 kh0 = Z4, kh1 = Z4, kl0 = Z4, kl1 = Z4;
        uint4 vh0 = Z4, vh1 = Z4, vl0 = Z4, vl1 = Z4;
        if (mrow < n) {
            int e = L[mrow];
            int i = e & 0x7fffffff;
            size_t base = (size_t)i * DFF + h * DHEAD + part * 16;
            if (e < 0) {
                kh0 = ((const uint4*)(g_khi + base))[0];
                kh1 = ((const uint4*)(g_khi + base))[1];
                kl0 = ((const uint4*)(g_klo + base))[0];
                kl1 = ((const uint4*)(g_klo + base))[1];
            }
            vh0 = ((const uint4*)(g_vhi + base))[0];
            vh1 = ((const uint4*)(g_vhi + base))[1];
            vl0 = ((const uint4*)(g_vlo + base))[0];
            vl1 = ((const uint4*)(g_vlo + base))[1];
        }
        int sof = mem * KVS + part * 16;
        *(uint4*)(sKh + sof) = kh0; *(uint4*)(sKh + sof + 8) = kh1;
        *(uint4*)(sKl + sof) = kl0; *(uint4*)(sKl + sof + 8) = kl1;
        *(uint4*)(sVh + sof) = vh0; *(uint4*)(sVh + sof + 8) = vh1;
        *(uint4*)(sVl + sof) = vl0; *(uint4*)(sVl + sof + 8) = vl1;
        __syncthreads();

#pragma unroll
        for (int ks = 0; ks < 4; ks++) {
            int kb = ks * 16;
            uint32_t ah[2][4], al[2][4], bh[2][2], bl[2][2];
#pragma unroll
            for (int i = 0; i < 2; i++) {
                uint32_t off = (uint32_t)(((kb + a_moff) * KVS + wm * 32 + i * 16 + a_coff) * 2);
                ldsm_x4_t(ah[i], uKh + off);
                ldsm_x4_t(al[i], uKl + off);
            }
#pragma unroll
            for (int j = 0; j < 2; j++) {
                uint32_t off = (uint32_t)(((kb + b_moff) * KVS + wn * 16 + j * 8) * 2);
                ldsm_x2_t(bh[j], uVh + off);
                ldsm_x2_t(bl[j], uVl + off);
            }
#pragma unroll
            for (int i = 0; i < 2; i++)
#pragma unroll
                for (int j = 0; j < 2; j++) {
                    mma_bf16(acc[i][j], ah[i], bh[j]);
                    mma_bf16(acc[i][j], ah[i], bl[j]);
                    mma_bf16(acc[i][j], al[i], bh[j]);
                }
        }
        __syncthreads();
    }

#pragma unroll
    for (int i = 0; i < 2; i++) {
        int a_r = wm * 32 + i * 16 + g;
#pragma unroll
        for (int j = 0; j < 2; j++) {
            int b_c = wn * 16 + j * 8 + tq * 2;
            __nv_bfloat16 h0, l0, h1, l1;
            split2(acc[i][j][0] * inv, h0, l0);
            split2(acc[i][j][1] * inv, h1, l1);
            *(__nv_bfloat162*)(sVh + a_r * KVS + b_c) = __nv_bfloat162(h0, h1);
            *(__nv_bfloat162*)(sVl + a_r * KVS + b_c) = __nv_bfloat162(l0, l1);
            split2(acc[i][j][2] * inv, h0, l0);
            split2(acc[i][j][3] * inv, h1, l1);
            *(__nv_bfloat162*)(sVh + (a_r + 8) * KVS + b_c) = __nv_bfloat162(h0, h1);
            *(__nv_bfloat162*)(sVl + (a_r + 8) * KVS + b_c) = __nv_bfloat162(l0, l1);
        }
    }
    __syncthreads();

    for (int ch = 0; ch < nchunks; ch++) {
        int mrow = ch * 64 + mem;
        uint4 qh0 = Z4, qh1 = Z4, ql0 = Z4, ql1 = Z4;
        if (mrow < n) {
            int i = L[mrow] & 0x7fffffff;
            size_t base = (size_t)i * DFF + h * DHEAD + part * 16;
            qh0 = ((const uint4*)(g_qhi + base))[0];
            qh1 = ((const uint4*)(g_qhi + base))[1];
            ql0 = ((const uint4*)(g_qlo + base))[0];
            ql1 = ((const uint4*)(g_qlo + base))[1];
        }
        int sof = mem * KVS + part * 16;
        *(uint4*)(sKh + sof) = qh0; *(uint4*)(sKh + sof + 8) = qh1;
        *(uint4*)(sKl + sof) = ql0; *(uint4*)(sKl + sof + 8) = ql1;
        __syncthreads();

        float acc2[2][2][4];
#pragma unroll
        for (int i = 0; i < 2; i++)
#pragma unroll
            for (int j = 0; j < 2; j++)
#pragma unroll
                for (int e = 0; e < 4; e++) acc2[i][j][e] = 0.f;

#pragma unroll
        for (int ks = 0; ks < 4; ks++) {
            int kb = ks * 16;
            uint32_t ah[2][4], al[2][4], bh[2][2], bl[2][2];
#pragma unroll
            for (int i = 0; i < 2; i++) {
                uint32_t off = (uint32_t)(((q_arow + i * 16) * KVS + kb + q_aksel) * 2);
                ldsm_x4(ah[i], uKh + off);
                ldsm_x4(al[i], uKl + off);
            }
#pragma unroll
            for (int j = 0; j < 2; j++) {
                uint32_t off = (uint32_t)(((a_brow + j * 8) * KVS + kb + a_bksel) * 2);
                ldsm_x2(bh[j], uVh + off);
                ldsm_x2(bl[j], uVl + off);
            }
#pragma unroll
            for (int i = 0; i < 2; i++)
#pragma unroll
                for (int j = 0; j < 2; j++) {
                    mma_bf16(acc2[i][j], ah[i], bh[j]);
                    mma_bf16(acc2[i][j], ah[i], bl[j]);
                    mma_bf16(acc2[i][j], al[i], bh[j]);
                }
        }

#pragma unroll
        for (int i = 0; i < 2; i++) {
            int mr0 = ch * 64 + wm * 32 + i * 16 + g;
#pragma unroll
            for (int j = 0; j < 2; j++) {
                int aa = wn * 16 + j * 8 + tq * 2;
                int colg = h * 128 + aa;
#pragma unroll
                for (int rr = 0; rr < 2; rr++) {
                    int mr = mr0 + rr * 8;
                    if (mr < n) {
                        int irow = L[mr] & 0x7fffffff;
                        int bb = batchv[irow];
                        float2 bm = *(const float2*)(g_bmean + (size_t)bb * YW + colg);
                        float v0 = acc2[i][j][rr * 2 + 0] + bm.x;
                        float v1 = acc2[i][j][rr * 2 + 1] + bm.y;
                        __nv_bfloat16 h0, l0, h1, l1;
                        split2(v0, h0, l0);
                        split2(v1, h1, l1);
                        *(__nv_bfloat162*)(g_yhi + (size_t)irow * YW + colg) = __nv_bfloat162(h0, h1);
                        *(__nv_bfloat162*)(g_ylo + (size_t)irow * YW + colg) = __nv_bfloat162(l0, l1);
                    }
                }
            }
        }
        __syncthreads();
    }
}

// ================= seg reduce =================
__global__ void __launch_bounds__(256) seg_red_kernel()
{
    int bid = blockIdx.x;
    int sh = bid >> 3, grp = bid & 7;
    int s = sh >> 3;
    int n = g_cnt_batch[s];
    float inv = g_minv_batch[s];
    int nch = (n + 63) >> 6;
    if (nch > KZ) nch = KZ;
    int e = grp * 512 + (threadIdx.x & 127) * 4;
    if (threadIdx.x >= 128) return;
    const float* P = g_Apart + (size_t)sh * 4096 + e;
    const size_t ZS = (size_t)64 * 4096;
    float4 a0 = make_float4(0.f, 0.f, 0.f, 0.f);
    float4 a1 = make_float4(0.f, 0.f, 0.f, 0.f);
    int z = 0;
    for (; z + 1 < nch; z += 2) {
        float4 p0 = *(const float4*)(P + (size_t)z * ZS);
        float4 p1 = *(const float4*)(P + (size_t)(z + 1) * ZS);
        a0.x += p0.x; a0.y += p0.y; a0.z += p0.z; a0.w += p0.w;
        a1.x += p1.x; a1.y += p1.y; a1.z += p1.z; a1.w += p1.w;
    }
    if (z < nch) {
        float4 p0 = *(const float4*)(P + (size_t)z * ZS);
        a0.x += p0.x; a0.y += p0.y; a0.z += p0.z; a0.w += p0.w;
    }
    float v0 = (a0.x + a1.x) * inv;
    float v1 = (a0.y + a1.y) * inv;
    float v2 = (a0.z + a1.z) * inv;
    float v3 = (a0.w + a1.w) * inv;
    __nv_bfloat16 h0, l0, h1, l1, h2, l2, h3, l3;
    split2(v0, h0, l0); split2(v1, h1, l1);
    split2(v2, h2, l2); split2(v3, h3, l3);
    *(__nv_bfloat162*)(g_Ahi + (size_t)sh * 4096 + e)     = __nv_bfloat162(h0, h1);
    *(__nv_bfloat162*)(g_Ahi + (size_t)sh * 4096 + e + 2) = __nv_bfloat162(h2, h3);
    *(__nv_bfloat162*)(g_Alo + (size_t)sh * 4096 + e)     = __nv_bfloat162(l0, l1);
    *(__nv_bfloat162*)(g_Alo + (size_t)sh * 4096 + e + 2) = __nv_bfloat162(l2, l3);
}

// ================= seg launch B: batch phase-2 chunk blocks =================
__global__ void __launch_bounds__(256) seg_b_kernel(const int* __restrict__ batchv)
{
    int bid = blockIdx.x;
    int kz = bid >> 6;
    int s  = (bid >> 3) & 7;
    int h  = bid & 7;
    int sh = s * 8 + h;
    const int* L = g_list_batch + s * BA_STRIDE;
    int n = g_cnt_batch[s];
    if (kz * 64 >= n) return;

    int t = threadIdx.x, wid = t >> 5, lane = t & 31;
    int wm = wid & 1, wn = wid >> 1;

    __shared__ __align__(16) __nv_bfloat16 sKh[64 * KVS];
    __shared__ __align__(16) __nv_bfloat16 sKl[64 * KVS];
    __shared__ __align__(16) __nv_bfloat16 sVh[64 * KVS];
    __shared__ __align__(16) __nv_bfloat16 sVl[64 * KVS];
    uint32_t uKh = smem_u32(sKh), uKl = smem_u32(sKl);
    uint32_t uVh = smem_u32(sVh), uVl = smem_u32(sVl);

    int mem = t >> 2, part = t & 3;
    int g = lane >> 2, tq = lane & 3;
    const uint4 Z4 = make_uint4(0, 0, 0, 0);

#pragma unroll
    for (int it = 0; it < 2; it++) {
        int idx = (it * 256 + t) * 8;
        int r = idx >> 6, c = idx & 63;
        *(uint4*)(sVh + r * KVS + c) = *(const uint4*)(g_Ahi + (size_t)sh * 4096 + idx);
        *(uint4*)(sVl + r * KVS + c) = *(const uint4*)(g_Alo + (size_t)sh * 4096 + idx);
    }
    int mrow = kz * 64 + mem;
    uint4 qh0 = Z4, qh1 = Z4, ql0 = Z4, ql1 = Z4;
    if (mrow < n) {
        int i = L[mrow] & 0x7fffffff;
        size_t base = (size_t)i * DFF + h * DHEAD + part * 16;
        qh0 = ((const uint4*)(g_qhi + base))[0];
        qh1 = ((const uint4*)(g_qhi + base))[1];
        ql0 = ((const uint4*)(g_qlo + base))[0];
        ql1 = ((const uint4*)(g_qlo + base))[1];
    }
    int sof = mem * KVS + part * 16;
    *(uint4*)(sKh + sof) = qh0; *(uint4*)(sKh + sof + 8) = qh1;
    *(uint4*)(sKl + sof) = ql0; *(uint4*)(sKl + sof + 8) = ql1;
    __syncthreads();

    int q_arow = wm * 32 + (lane & 15);
    int q_aksel = (lane >> 4) * 8;
    int a_brow = wn * 16 + (lane & 7);
    int a_bksel = ((lane >> 3) & 1) * 8;

    float acc2[2][2][4];
#pragma unroll
    for (int i = 0; i < 2; i++)
#pragma unroll
        for (int j = 0; j < 2; j++)
#pragma unroll
            for (int e = 0; e < 4; e++) acc2[i][j][e] = 0.f;

#pragma unroll
    for (int ks = 0; ks < 4; ks++) {
        int kb = ks * 16;
        uint32_t ah[2][4], al[2][4], bh[2][2], bl[2][2];
#pragma unroll
        for (int i = 0; i < 2; i++) {
            uint32_t off = (uint32_t)(((q_arow + i * 16) * KVS + kb + q_aksel) * 2);
            ldsm_x4(ah[i], uKh + off);
            ldsm_x4(al[i], uKl + off);
        }
#pragma unroll
        for (int j = 0; j < 2; j++) {
            uint32_t off = (uint32_t)(((a_brow + j * 8) * KVS + kb + a_bksel) * 2);
            ldsm_x2(bh[j], uVh + off);
            ldsm_x2(bl[j], uVl + off);
        }
#pragma unroll
        for (int i = 0; i < 2; i++)
#pragma unroll
            for (int j = 0; j < 2; j++) {
                mma_bf16(acc2[i][j], ah[i], bh[j]);
                mma_bf16(acc2[i][j], ah[i], bl[j]);
                mma_bf16(acc2[i][j], al[i], bh[j]);
            }
    }

#pragma unroll
    for (int i = 0; i < 2; i++) {
        int mr0 = kz * 64 + wm * 32 + i * 16 + g;
#pragma unroll
        for (int j = 0; j < 2; j++) {
            int aa = wn * 16 + j * 8 + tq * 2;
            int colg = h * 128 + DHEAD + aa;
#pragma unroll
            for (int rr = 0; rr < 2; rr++) {
                int mr = mr0 + rr * 8;
                if (mr < n) {
                    int irow = L[mr] & 0x7fffffff;
                    int bb = batchv[irow];
                    float2 bm = *(const float2*)(g_bmean + (size_t)bb * YW + colg);
                    float v0 = acc2[i][j][rr * 2 + 0] + bm.x;
                    float v1 = acc2[i][j][rr * 2 + 1] + bm.y;
                    __nv_bfloat16 h0, l0, h1, l1;
                    split2(v0, h0, l0);
                    split2(v1, h1, l1);
                    *(__nv_bfloat162*)(g_yhi + (size_t)irow * YW + colg) = __nv_bfloat162(h0, h1);
                    *(__nv_bfloat162*)(g_ylo + (size_t)irow * YW + colg) = __nv_bfloat162(l0, l1);
                }
            }
        }
    }
}

// ================= launch =================
extern "C" void kernel_launch(void* const* d_in, const int* in_sizes, int n_in,
                              void* d_out, int out_size)
{
    const float* local   = (const float*)d_in[0];
    const int*   chain   = (const int*)  d_in[1];
    const int*   batch   = (const int*)  d_in[2];
    const void*  mask    = d_in[3];
    const float* W_key   = (const float*)d_in[4];
    const float* b_key   = (const float*)d_in[5];
    const float* W_value = (const float*)d_in[6];
    const float* b_value = (const float*)d_in[7];
    const float* W_query = (const float*)d_in[8];
    const float* b_query = (const float*)d_in[9];
    const float* W_bias  = (const float*)d_in[10];
    const float* b_bias  = (const float*)d_in[11];
    const float* W_out   = (const float*)d_in[12];
    float* out = (float*)d_out;

    static cudaStream_t s2 = nullptr;
    static cudaEvent_t evFork = nullptr, evJoin = nullptr;
    static bool attr_done = false;
    if (!attr_done) {
        cudaFuncSetAttribute(proj_mma_kernel, cudaFuncAttributeMaxDynamicSharedMemorySize, PROJ_SMEM);
        cudaFuncSetAttribute(out_mma_kernel,  cudaFuncAttributeMaxDynamicSharedMemorySize, OUT_SMEM);
        cudaStreamCreateWithFlags(&s2, cudaStreamNonBlocking);
        cudaEventCreateWithFlags(&evFork, cudaEventDisableTiming);
        cudaEventCreateWithFlags(&evJoin, cudaEventDisableTiming);
        attr_done = true;
    }

    // fork: build_all on s2, prep+proj on main stream
    cudaEventRecord(evFork, 0);
    cudaStreamWaitEvent(s2, evFork, 0);

    build_all_kernel<<<NBATCH + NCHAIN, 1024, 0, s2>>>(chain, batch, mask, local, W_bias, b_bias);
    cudaEventRecord(evJoin, s2);

    prep_kernel<<<3072, 256>>>(local, W_key, W_value, W_query, W_out);
    proj_mma_kernel<<<dim3(1536 / 128, NROWS / 128), 256, PROJ_SMEM>>>(b_key, b_value, b_query);

    // join: seg needs both build_all (lists/bmean) and proj (k/v/q splits)
    cudaStreamWaitEvent(0, evJoin, 0);

    seg_a_kernel<<<NCHAIN * NHEAD + KZ * NBATCH * NHEAD, 256>>>(batch);
    seg_red_kernel<<<NBATCH * NHEAD * 8, 256>>>();
    seg_b_kernel<<<KZ * NBATCH * NHEAD, 256>>>(batch);

    out_mma_kernel<<<dim3(DIM / 128, NROWS / 64), 256, OUT_SMEM>>>(out);
}